// round 3
// baseline (speedup 1.0000x reference)
#include <cuda_runtime.h>

// Problem constants (fixed shapes from reference)
#define BB   2
#define NN   16384
#define MM   4096
#define CC   64
#define KK   16
#define TILE 2048
#define WPB  8          // warps (queries) per block
#define NQ   (BB * MM)  // 8192 total queries
#define UNR  8          // candidates per lane per chunk

#define BIGF 1e30f

// Scratch (__device__ globals; no allocs allowed)
__device__ float  g_xt[BB * NN * CC];    // transposed features (B,N,C), 8 MB
__device__ float4 g_pts[BB * NN];        // packed points (x,y,z,|p|^2), 512 KB

// ---------------------------------------------------------------------------
// monotone float<->int map (order-preserving for ALL floats incl. negatives)
// ---------------------------------------------------------------------------
__device__ __forceinline__ int f2mono(float f) {
    int b = __float_as_int(f);
    return b ^ ((b >> 31) & 0x7fffffff);
}
__device__ __forceinline__ float mono2f(int m) {
    return __int_as_float(m ^ ((m >> 31) & 0x7fffffff));
}

// ---------------------------------------------------------------------------
// Kernel 0: pack p1 (B,N,3) -> (x,y,z,|p|^2) float4
// ---------------------------------------------------------------------------
__global__ __launch_bounds__(256) void pack_kernel(const float* __restrict__ p1) {
    const int i = blockIdx.x * 256 + threadIdx.x;  // 0 .. BB*NN-1
    const float x = p1[i * 3 + 0];
    const float y = p1[i * 3 + 1];
    const float z = p1[i * 3 + 2];
    g_pts[i] = make_float4(x, y, z, fmaf(x, x, fmaf(y, y, z * z)));
}

// ---------------------------------------------------------------------------
// Kernel 1: transpose x1 (B,C,N) -> g_xt (B,N,C) so neighbor gathers coalesce.
// ---------------------------------------------------------------------------
__global__ __launch_bounds__(256) void transpose_kernel(const float* __restrict__ x1) {
    __shared__ float t[32][33];
    const int b  = blockIdx.z;
    const int n0 = blockIdx.x * 32;
    const int c0 = blockIdx.y * 32;
    const int tx = threadIdx.x;
    const int ty = threadIdx.y;

    const float* src = x1  + (size_t)b * CC * NN;
    float*       dst = g_xt + (size_t)b * NN * CC;

#pragma unroll
    for (int i = 0; i < 32; i += 8)
        t[ty + i][tx] = src[(size_t)(c0 + ty + i) * NN + (n0 + tx)];
    __syncthreads();
#pragma unroll
    for (int i = 0; i < 32; i += 8)
        dst[(size_t)(n0 + ty + i) * CC + (c0 + tx)] = t[tx][ty + i];
}

// ---------------------------------------------------------------------------
// Kernel 2: per-warp exact KNN(16) + fused feature gather/mean.
// One warp per query. Points tiled through shared as float4 (x,y,z,|p|^2).
// Ranking metric d' = |p|^2 - 2 q.p  (== |p-q|^2 - |q|^2, same order per q).
// Per-lane top-16 in registers; warp-shared gate tau refreshed EVERY chunk
// via REDUX.SYNC.MIN (tau = min over lanes of lane-worst; d >= tau provably
// cannot be in the global top-16).
// ---------------------------------------------------------------------------
__global__ __launch_bounds__(32 * WPB) void knn_kernel(const float* __restrict__ p2,
                                                       float* __restrict__ out) {
    __shared__ float4 sp[TILE];   // 32 KB

    const int warp = threadIdx.x >> 5;
    const int lane = threadIdx.x & 31;
    const int q    = blockIdx.x * WPB + warp;
    const int b    = q >> 12;          // q / MM
    const int m    = q & (MM - 1);

    const float qx = p2[((size_t)b * MM + m) * 3 + 0];
    const float qy = p2[((size_t)b * MM + m) * 3 + 1];
    const float qz = p2[((size_t)b * MM + m) * 3 + 2];
    const float nqx = -2.0f * qx, nqy = -2.0f * qy, nqz = -2.0f * qz;

    const float4* gp = g_pts + (size_t)b * NN;

    float bd[KK];
    int   bi[KK];
#pragma unroll
    for (int k = 0; k < KK; k++) { bd[k] = BIGF; bi[k] = 0; }
    float worst    = BIGF;
    int   worstpos = 0;
    float thr      = BIGF;

    for (int t0 = 0; t0 < NN; t0 += TILE) {
        __syncthreads();
        for (int i = threadIdx.x; i < TILE; i += 32 * WPB)
            sp[i] = gp[t0 + i];
        __syncthreads();

        for (int jc = 0; jc < TILE; jc += UNR * 32) {
            float d[UNR];
#pragma unroll
            for (int u = 0; u < UNR; u++) {
                const float4 P = sp[jc + u * 32 + lane];
                d[u] = fmaf(nqx, P.x, fmaf(nqy, P.y, fmaf(nqz, P.z, P.w)));
            }
            bool ins = false;
#pragma unroll
            for (int u = 0; u < UNR; u++) ins |= (d[u] < thr);

            if (__any_sync(0xffffffffu, ins)) {
#pragma unroll
                for (int u = 0; u < UNR; u++) {
                    if (d[u] < thr) {
                        const int t = t0 + jc + u * 32 + lane;
#pragma unroll
                        for (int k = 0; k < KK; k++)
                            if (k == worstpos) { bd[k] = d[u]; bi[k] = t; }
                        worst = bd[0]; worstpos = 0;
#pragma unroll
                        for (int k = 1; k < KK; k++)
                            if (bd[k] > worst) { worst = bd[k]; worstpos = k; }
                        thr = fminf(thr, worst);
                    }
                }
            }
            // tau = warp-min of lane worsts (safe gate), one REDUX
            thr = mono2f(__reduce_min_sync(0xffffffffu, f2mono(worst)));
        }
    }

    // --- per-lane bitonic sort (ascending), static indices ---
#pragma unroll
    for (int sz = 2; sz <= KK; sz <<= 1) {
#pragma unroll
        for (int st = sz >> 1; st > 0; st >>= 1) {
#pragma unroll
            for (int i = 0; i < KK; i++) {
                const int jj = i ^ st;
                if (jj > i) {
                    const bool up = ((i & sz) == 0);
                    const bool sw = (bd[i] > bd[jj]) == up;
                    const float td = sw ? bd[jj] : bd[i];
                    const float td2 = sw ? bd[i] : bd[jj];
                    const int   ti = sw ? bi[jj] : bi[i];
                    const int   ti2 = sw ? bi[i] : bi[jj];
                    bd[i] = td; bd[jj] = td2;
                    bi[i] = ti; bi[jj] = ti2;
                }
            }
        }
    }

    // --- 16-round warp k-way merge fused with feature gather ---
    const float* ft = g_xt + (size_t)b * NN * CC;
    int   p  = 0;
    float a0 = 0.0f, a1 = 0.0f;
#pragma unroll 1
    for (int r = 0; r < KK; r++) {
        float hv = BIGF; int hi = 0;
#pragma unroll
        for (int k = 0; k < KK; k++)
            if (k == p) { hv = bd[k]; hi = bi[k]; }
        float v  = hv;
        int   ln = lane;
#pragma unroll
        for (int off = 16; off; off >>= 1) {
            const float ov = __shfl_xor_sync(0xffffffffu, v, off);
            const int   ol = __shfl_xor_sync(0xffffffffu, ln, off);
            if (ov < v || (ov == v && ol < ln)) { v = ov; ln = ol; }
        }
        const int gidx = __shfl_sync(0xffffffffu, hi, ln);
        p += (lane == ln) ? 1 : 0;
        const float* f = ft + (size_t)gidx * CC;
        a0 += f[lane];
        a1 += f[lane + 32];
    }

    out[((size_t)b * CC + lane) * MM + m]      = a0 * (1.0f / KK);
    out[((size_t)b * CC + lane + 32) * MM + m] = a1 * (1.0f / KK);
}

// ---------------------------------------------------------------------------
extern "C" void kernel_launch(void* const* d_in, const int* in_sizes, int n_in,
                              void* d_out, int out_size) {
    const float* p1 = (const float*)d_in[0];   // (B, N, 3)
    const float* x1 = (const float*)d_in[1];   // (B, C, N)
    const float* p2 = (const float*)d_in[2];   // (B, M, 3)
    float* out = (float*)d_out;                // (B, C, M)

    pack_kernel<<<(BB * NN) / 256, 256>>>(p1);

    dim3 tb(32, 8);
    dim3 tg(NN / 32, CC / 32, BB);
    transpose_kernel<<<tg, tb>>>(x1);

    knn_kernel<<<NQ / WPB, 32 * WPB>>>(p2, out);
}

// round 6
// speedup vs baseline: 6.8055x; 6.8055x over previous
#include <cuda_runtime.h>

// Problem constants (fixed shapes from reference)
#define BB   2
#define NN   16384
#define MM   4096
#define CC   64
#define KK   16
#define TILE 2048
#define WPB  8          // warps (queries) per block
#define NQ   (BB * MM)  // 8192 total queries

#define BIGF 1e30f
#define FULLMASK 0xffffffffu

// Scratch (__device__ globals; no allocs allowed)
__device__ float g_xt[BB * NN * CC];   // transposed features (B,N,C), 8 MB
__device__ float g_px[BB * NN];        // SoA packed points + |p|^2
__device__ float g_py[BB * NN];
__device__ float g_pz[BB * NN];
__device__ float g_pw[BB * NN];

// ---------------------------------------------------------------------------
// Kernel 0: pack p1 (B,N,3) -> SoA (x, y, z, |p|^2)
// ---------------------------------------------------------------------------
__global__ __launch_bounds__(256) void pack_kernel(const float* __restrict__ p1) {
    const int i = blockIdx.x * 256 + threadIdx.x;  // 0 .. BB*NN-1
    const float x = p1[i * 3 + 0];
    const float y = p1[i * 3 + 1];
    const float z = p1[i * 3 + 2];
    g_px[i] = x; g_py[i] = y; g_pz[i] = z;
    g_pw[i] = fmaf(x, x, fmaf(y, y, z * z));
}

// ---------------------------------------------------------------------------
// Kernel 1: transpose x1 (B,C,N) -> g_xt (B,N,C) so neighbor gathers coalesce.
// ---------------------------------------------------------------------------
__global__ __launch_bounds__(256) void transpose_kernel(const float* __restrict__ x1) {
    __shared__ float t[32][33];
    const int b  = blockIdx.z;
    const int n0 = blockIdx.x * 32;
    const int c0 = blockIdx.y * 32;
    const int tx = threadIdx.x;
    const int ty = threadIdx.y;

    const float* src = x1  + (size_t)b * CC * NN;
    float*       dst = g_xt + (size_t)b * NN * CC;

#pragma unroll
    for (int i = 0; i < 32; i += 8)
        t[ty + i][tx] = src[(size_t)(c0 + ty + i) * NN + (n0 + tx)];
    __syncthreads();
#pragma unroll
    for (int i = 0; i < 32; i += 8)
        dst[(size_t)(n0 + ty + i) * CC + (c0 + tx)] = t[tx][ty + i];
}

// ---------------------------------------------------------------------------
// Kernel 2: warp-distributed exact KNN(16) + fused gather/mean.
// One warp per query. Lanes 0..15 hold the current GLOBAL top-16 sorted
// ascending (topd/topi); lane 15 is the exact running 16th distance = gate.
// Hot path: 4 LDS + 3 FFMA + ballot. Inserts are warp-cooperative ranked
// shifts behind a warp-UNIFORM branch (ballot != 0) -> no divergence cost.
// Ranking metric d' = |p|^2 - 2 q.p (order-equivalent to squared distance).
// ---------------------------------------------------------------------------
__global__ __launch_bounds__(32 * WPB) void knn_kernel(const float* __restrict__ p2,
                                                       float* __restrict__ out) {
    __shared__ float sx[TILE];
    __shared__ float sy[TILE];
    __shared__ float sz[TILE];
    __shared__ float sw[TILE];   // 32 KB total

    const int warp = threadIdx.x >> 5;
    const int lane = threadIdx.x & 31;
    const int q    = blockIdx.x * WPB + warp;
    const int b    = q >> 12;          // q / MM
    const int m    = q & (MM - 1);

    const float qx = p2[((size_t)b * MM + m) * 3 + 0];
    const float qy = p2[((size_t)b * MM + m) * 3 + 1];
    const float qz = p2[((size_t)b * MM + m) * 3 + 2];
    const float nqx = -2.0f * qx, nqy = -2.0f * qy, nqz = -2.0f * qz;

    const int pb = b * NN;   // batch offset into point arrays

    float topd = BIGF;       // lanes 0..15: sorted top-16 (ascending)
    int   topi = 0;
    float tau  = BIGF;       // = topd at lane 15 (exact global 16th so far)

    for (int t0 = 0; t0 < NN; t0 += TILE) {
        __syncthreads();
        {
            const float4* px4 = (const float4*)(g_px + pb + t0);
            const float4* py4 = (const float4*)(g_py + pb + t0);
            const float4* pz4 = (const float4*)(g_pz + pb + t0);
            const float4* pw4 = (const float4*)(g_pw + pb + t0);
#pragma unroll
            for (int i = threadIdx.x; i < TILE / 4; i += 32 * WPB) {
                ((float4*)sx)[i] = px4[i];
                ((float4*)sy)[i] = py4[i];
                ((float4*)sz)[i] = pz4[i];
                ((float4*)sw)[i] = pw4[i];
            }
        }
        __syncthreads();

#pragma unroll 4
        for (int j = 0; j < TILE / 32; j++) {
            const int t = j * 32 + lane;
            const float d = fmaf(nqx, sx[t], fmaf(nqy, sy[t], fmaf(nqz, sz[t], sw[t])));
            unsigned bal = __ballot_sync(FULLMASK, d < tau);
            if (bal) {                       // warp-uniform branch
                const int myidx = t0 + j * 32 + lane;
                do {
                    const int src = __ffs(bal) - 1;
                    bal &= bal - 1;
                    const float dc = __shfl_sync(FULLMASK, d, src);
                    const int   ic = __shfl_sync(FULLMASK, myidx, src);
                    // rank = #elements smaller (list sorted -> contiguous mask)
                    const unsigned m16 = __ballot_sync(FULLMASK, topd < dc) & 0xFFFFu;
                    const int rank = __popc(m16);
                    const float pd = __shfl_up_sync(FULLMASK, topd, 1);
                    const int   pi = __shfl_up_sync(FULLMASK, topi, 1);
                    if (lane == rank)      { topd = dc; topi = ic; }
                    else if (lane > rank)  { topd = pd; topi = pi; }
                } while (bal);
                tau = __shfl_sync(FULLMASK, topd, 15);
            }
        }
    }

    // --- fused gather/mean: lanes 0..15 already hold sorted top-16 ---
    const float* ft = g_xt + (size_t)b * NN * CC;
    float a0 = 0.0f, a1 = 0.0f;
#pragma unroll
    for (int r = 0; r < KK; r++) {
        const int g = __shfl_sync(FULLMASK, topi, r);
        const float* f = ft + (size_t)g * CC;
        a0 += f[lane];
        a1 += f[lane + 32];
    }

    out[((size_t)b * CC + lane) * MM + m]      = a0 * (1.0f / KK);
    out[((size_t)b * CC + lane + 32) * MM + m] = a1 * (1.0f / KK);
}

// ---------------------------------------------------------------------------
extern "C" void kernel_launch(void* const* d_in, const int* in_sizes, int n_in,
                              void* d_out, int out_size) {
    const float* p1 = (const float*)d_in[0];   // (B, N, 3)
    const float* x1 = (const float*)d_in[1];   // (B, C, N)
    const float* p2 = (const float*)d_in[2];   // (B, M, 3)
    float* out = (float*)d_out;                // (B, C, M)

    pack_kernel<<<(BB * NN) / 256, 256>>>(p1);

    dim3 tb(32, 8);
    dim3 tg(NN / 32, CC / 32, BB);
    transpose_kernel<<<tg, tb>>>(x1);

    knn_kernel<<<NQ / WPB, 32 * WPB>>>(p2, out);
}

// round 8
// speedup vs baseline: 7.8542x; 1.1541x over previous
#include <cuda_runtime.h>

// Problem constants (fixed shapes from reference)
#define BB   2
#define NN   16384
#define MM   4096
#define CC   64
#define KK   16
#define TILE 2048
#define WPB  8          // warps per block (each warp = 2 queries)
#define NQ   (BB * MM)  // 8192 total queries
#define NP   (NQ / 2)   // 4096 query-pairs (one per warp)

#define BIGF 1e30f
#define FULLMASK 0xffffffffu

// Scratch (__device__ globals; no allocs allowed)
__device__ float  g_xt[BB * NN * CC];   // transposed features (B,N,C), 8 MB
__device__ float4 g_pts[BB * NN];       // packed points (x,y,z,|p|^2)

// ---------------------------------------------------------------------------
// Kernel 0: pack p1 (B,N,3) -> float4 (x, y, z, |p|^2)
// ---------------------------------------------------------------------------
__global__ __launch_bounds__(256) void pack_kernel(const float* __restrict__ p1) {
    const int i = blockIdx.x * 256 + threadIdx.x;  // 0 .. BB*NN-1
    const float x = p1[i * 3 + 0];
    const float y = p1[i * 3 + 1];
    const float z = p1[i * 3 + 2];
    g_pts[i] = make_float4(x, y, z, fmaf(x, x, fmaf(y, y, z * z)));
}

// ---------------------------------------------------------------------------
// Kernel 1: transpose x1 (B,C,N) -> g_xt (B,N,C) so neighbor gathers coalesce.
// ---------------------------------------------------------------------------
__global__ __launch_bounds__(256) void transpose_kernel(const float* __restrict__ x1) {
    __shared__ float t[32][33];
    const int b  = blockIdx.z;
    const int n0 = blockIdx.x * 32;
    const int c0 = blockIdx.y * 32;
    const int tx = threadIdx.x;
    const int ty = threadIdx.y;

    const float* src = x1  + (size_t)b * CC * NN;
    float*       dst = g_xt + (size_t)b * NN * CC;

#pragma unroll
    for (int i = 0; i < 32; i += 8)
        t[ty + i][tx] = src[(size_t)(c0 + ty + i) * NN + (n0 + tx)];
    __syncthreads();
#pragma unroll
    for (int i = 0; i < 32; i += 8)
        dst[(size_t)(n0 + ty + i) * CC + (c0 + tx)] = t[tx][ty + i];
}

// ---------------------------------------------------------------------------
// Kernel 2: warp-distributed exact KNN(16) for TWO queries per warp,
// + fused feature gather/mean.
// Lanes 0..15 hold query-0's global top-16 sorted ascending; lanes 16..31
// hold query-1's. Hot path per 32 points (64 evals): 1 LDS.128 + 6 FFMA +
// 2 ballots. Inserts are warp-cooperative ranked shifts behind warp-uniform
// branches. Ranking metric d' = |p|^2 - 2 q.p (order-equiv to |p-q|^2).
// ---------------------------------------------------------------------------
__global__ __launch_bounds__(32 * WPB) void knn_kernel(const float* __restrict__ p2,
                                                       float* __restrict__ out) {
    __shared__ float4 sp[TILE];   // 32 KB

    const int warp = threadIdx.x >> 5;
    const int lane = threadIdx.x & 31;
    const int P    = blockIdx.x * WPB + warp;   // 0..NP-1
    const int b    = P >> 11;                   // P / (MM/2)
    const int m0   = (P & 2047) * 2;            // first query index
                                                // second query = m0 + 1
    const float* qp = p2 + ((size_t)b * MM + m0) * 3;
    const float n0x = -2.0f * qp[0], n0y = -2.0f * qp[1], n0z = -2.0f * qp[2];
    const float n1x = -2.0f * qp[3], n1y = -2.0f * qp[4], n1z = -2.0f * qp[5];

    const float4* gp = g_pts + (size_t)b * NN;

    float topd = BIGF;      // sorted top-16: q0 in lanes 0..15, q1 in 16..31
    int   topi = 0;
    float tau0 = BIGF;      // exact running 16th for q0  (= topd @ lane 15)
    float tau1 = BIGF;      // exact running 16th for q1  (= topd @ lane 31)

    for (int t0 = 0; t0 < NN; t0 += TILE) {
        __syncthreads();
        for (int i = threadIdx.x; i < TILE; i += 32 * WPB)
            sp[i] = gp[t0 + i];
        __syncthreads();

#pragma unroll 8
        for (int j = 0; j < TILE / 32; j++) {
            const float4 Pt = sp[j * 32 + lane];
            const float d0 = fmaf(n0x, Pt.x, fmaf(n0y, Pt.y, fmaf(n0z, Pt.z, Pt.w)));
            const float d1 = fmaf(n1x, Pt.x, fmaf(n1y, Pt.y, fmaf(n1z, Pt.z, Pt.w)));
            unsigned bal0 = __ballot_sync(FULLMASK, d0 < tau0);
            unsigned bal1 = __ballot_sync(FULLMASK, d1 < tau1);
            if (bal0 | bal1) {                 // warp-uniform
                const int myidx = t0 + j * 32 + lane;
                if (bal0) {                    // warp-uniform
                    do {
                        const int src = __ffs(bal0) - 1;
                        bal0 &= bal0 - 1;
                        const float dc = __shfl_sync(FULLMASK, d0, src);
                        const int   ic = __shfl_sync(FULLMASK, myidx, src);
                        const int rank = __popc(__ballot_sync(FULLMASK, topd < dc) & 0xFFFFu);
                        const float pd = __shfl_up_sync(FULLMASK, topd, 1);
                        const int   pi = __shfl_up_sync(FULLMASK, topi, 1);
                        if (lane < 16) {
                            if (lane == rank)     { topd = dc; topi = ic; }
                            else if (lane > rank) { topd = pd; topi = pi; }
                        }
                    } while (bal0);
                    tau0 = __shfl_sync(FULLMASK, topd, 15);
                }
                if (bal1) {                    // warp-uniform
                    do {
                        const int src = __ffs(bal1) - 1;
                        bal1 &= bal1 - 1;
                        const float dc = __shfl_sync(FULLMASK, d1, src);
                        const int   ic = __shfl_sync(FULLMASK, myidx, src);
                        const int rank = 16 + __popc(__ballot_sync(FULLMASK, topd < dc) >> 16);
                        const float pd = __shfl_up_sync(FULLMASK, topd, 1);
                        const int   pi = __shfl_up_sync(FULLMASK, topi, 1);
                        if (lane >= 16) {
                            if (lane == rank)     { topd = dc; topi = ic; }
                            else if (lane > rank) { topd = pd; topi = pi; }
                        }
                    } while (bal1);
                    tau1 = __shfl_sync(FULLMASK, topd, 31);
                }
            }
        }
    }

    // --- fused gather/mean for both queries (lists already sorted) ---
    const float* ft = g_xt + (size_t)b * NN * CC;
    float a0 = 0.0f, a1 = 0.0f;   // q0: channels [lane], [lane+32]
    float c0 = 0.0f, c1 = 0.0f;   // q1
#pragma unroll
    for (int r = 0; r < KK; r++) {
        const int g0 = __shfl_sync(FULLMASK, topi, r);
        const int g1 = __shfl_sync(FULLMASK, topi, 16 + r);
        const float* f0 = ft + (size_t)g0 * CC;
        const float* f1 = ft + (size_t)g1 * CC;
        a0 += f0[lane];
        a1 += f0[lane + 32];
        c0 += f1[lane];
        c1 += f1[lane + 32];
    }

    const size_t obase = ((size_t)b * CC + lane) * MM + m0;
    out[obase]                      = a0 * (1.0f / KK);
    out[obase + (size_t)32 * MM]    = a1 * (1.0f / KK);
    out[obase + 1]                  = c0 * (1.0f / KK);
    out[obase + (size_t)32 * MM + 1] = c1 * (1.0f / KK);
}

// ---------------------------------------------------------------------------
extern "C" void kernel_launch(void* const* d_in, const int* in_sizes, int n_in,
                              void* d_out, int out_size) {
    const float* p1 = (const float*)d_in[0];   // (B, N, 3)
    const float* x1 = (const float*)d_in[1];   // (B, C, N)
    const float* p2 = (const float*)d_in[2];   // (B, M, 3)
    float* out = (float*)d_out;                // (B, C, M)

    pack_kernel<<<(BB * NN) / 256, 256>>>(p1);

    dim3 tb(32, 8);
    dim3 tg(NN / 32, CC / 32, BB);
    transpose_kernel<<<tg, tb>>>(x1);

    knn_kernel<<<NP / WPB, 32 * WPB>>>(p2, out);
}